// round 7
// baseline (speedup 1.0000x reference)
#include <cuda_runtime.h>
#include <cstdint>

// ============================================================================
// NAS LSTM controller, 32 sequential steps, single persistent kernel.
// 64 CTAs x 512 threads, grid barrier via global atomics (all CTAs resident:
// 1 CTA/SM due to 202KB smem, 64 <= 148 SMs). Weights cached in SMEM.
// Exact JAX threefry2x32 (partitionable mode) for categorical sampling,
// replicated identically in every CTA (deterministic, no broadcast needed).
// ============================================================================

#define GRID  64
#define NT    512
#define D     512
#define LP1   33          // L+1 anchors
#define NSTEP 32
#define OPSN  16

// ------------------------------ global state -------------------------------
__device__ float    gHa[D];                // h after cell1
__device__ float    gHb[D];                // h after cell2 / init cell
__device__ float    gAnchors[LP1 * D];
__device__ float    gPart[LP1 * GRID];     // node-logit partials [anchor][cta]
__device__ unsigned gCount = 0;
__device__ unsigned gGen   = 0;

// ------------------------------ shared layout ------------------------------
struct SM {
    float W[32 * 1024];        // 32 gate rows: [w_ih row | w_hh row]   128 KB
    float A1[8 * D];           // rows 8b..8b+8 of w_attn_1              16 KB
    float A2[8 * D];           // rows 8b..8b+8 of w_attn_2              16 KB
    float OPF[OPSN * D];       // full op_fc                             32 KB
    float xbuf[D];
    float hfull[D];
    float bias[32];            // b_ih + b_hh for owned gate rows
    float gbuf[32];            // gate pre-activations
    float idxfc8[8];           // index_fc slice for owned dims
    float hw2s[8];             // (h @ w_attn_2^T) slice
    float anchW1loc[LP1 * 8];  // local slice of anchors_w1
    float cslice[8];           // owned c dims
    float vals[LP1];           // logits scratch
    float draws[LP1];          // gumbel-perturbed logits
    unsigned keyw[2];          // running PRNG key
    unsigned split6[6];        // 3 child keys from split
    int   nodeIdx;
    int   opIdx;
    float nodeLp, nodeEnt;
    float lpSum, entSum;
};

// ------------------------------ grid barrier -------------------------------
__device__ __forceinline__ void gbar(int tid) {
    __syncthreads();
    if (tid == 0) {
        __threadfence();
        volatile unsigned* vg = (volatile unsigned*)&gGen;
        unsigned gen = *vg;                       // snapshot BEFORE arriving
        if (atomicAdd(&gCount, 1u) == GRID - 1u) {
            atomicExch(&gCount, 0u);
            __threadfence();
            atomicAdd(&gGen, 1u);
        } else {
            while (*vg == gen) { }
        }
        __threadfence();
    }
    __syncthreads();
}

// ------------------------------ threefry2x32 -------------------------------
__device__ __forceinline__ void tf2x32(unsigned k0, unsigned k1,
                                       unsigned x0, unsigned x1,
                                       unsigned& o0, unsigned& o1) {
    unsigned ks2 = k0 ^ k1 ^ 0x1BD11BDAu;
    x0 += k0; x1 += k1;
#define TFR(r) { x0 += x1; x1 = (x1 << (r)) | (x1 >> (32 - (r))); x1 ^= x0; }
    TFR(13) TFR(15) TFR(26) TFR(6)   x0 += k1;  x1 += ks2 + 1u;
    TFR(17) TFR(29) TFR(16) TFR(24)  x0 += ks2; x1 += k0 + 2u;
    TFR(13) TFR(15) TFR(26) TFR(6)   x0 += k0;  x1 += k1 + 3u;
    TFR(17) TFR(29) TFR(16) TFR(24)  x0 += k1;  x1 += ks2 + 4u;
    TFR(13) TFR(15) TFR(26) TFR(6)   x0 += ks2; x1 += k0 + 5u;
#undef TFR
    o0 = x0; o1 = x1;
}

// Gumbel exactly as JAX: f from top 23 bits; u = max(tiny, f*(1-tiny)+tiny).
// (1-tiny) rounds to 1.0f so u == f except f==0 -> tiny; identical to XLA.
__device__ __forceinline__ float gumbelf(unsigned bits) {
    float f = __uint_as_float((bits >> 9) | 0x3f800000u) - 1.0f;
    const float tiny = 1.17549435e-38f;
    float u = fmaxf(tiny, f * (1.0f - tiny) + tiny);
    return -logf(-logf(u));
}

__device__ __forceinline__ float sigf(float x) {
    return 1.0f / (1.0f + expf(-x));
}

// LSTM cell phase: this CTA computes its 32 gate rows then its 8-dim (h,c)
// slice; writes the h slice to gout.
__device__ __forceinline__ void cell_phase(SM* s, int tid, int b, float* gout) {
    int row = tid >> 4, lane = tid & 15;        // 32 rows x 16 lanes
    const float4* wp = (const float4*)&s->W[row * 1024 + lane * 64];
    const float4* vp = (lane < 8) ? (const float4*)&s->xbuf[lane * 64]
                                  : (const float4*)&s->hfull[(lane - 8) * 64];
    float acc = 0.f;
#pragma unroll
    for (int i = 0; i < 16; i++) {
        float4 w = wp[i], v = vp[i];
        acc += w.x * v.x + w.y * v.y + w.z * v.z + w.w * v.w;
    }
#pragma unroll
    for (int o = 8; o; o >>= 1) acc += __shfl_down_sync(0xffffffffu, acc, o, 16);
    if (lane == 0) s->gbuf[row] = acc + s->bias[row];
    __syncthreads();
    if (tid < 8) {
        float gi = s->gbuf[tid],      gf = s->gbuf[8 + tid];
        float gg = s->gbuf[16 + tid], go = s->gbuf[24 + tid];
        float c2 = sigf(gf) * s->cslice[tid] + sigf(gi) * tanhf(gg);
        float h2 = sigf(go) * tanhf(c2);
        s->cslice[tid] = c2;
        gout[b * 8 + tid] = h2;
    }
}

// 8 dots of an 8x512 matrix slice with v -> dst[0..8). Uses threads 0..127.
__device__ __forceinline__ void attn_dot(const float* M, const float* v,
                                         float* dst, int tid) {
    if (tid < 128) {
        int r = tid >> 4, lane = tid & 15;      // 8 rows x 16 lanes x 32 elems
        const float4* mp = (const float4*)&M[r * 512 + lane * 32];
        const float4* vp = (const float4*)&v[lane * 32];
        float acc = 0.f;
#pragma unroll
        for (int i = 0; i < 8; i++) {
            float4 w = mp[i], x = vp[i];
            acc += w.x * x.x + w.y * x.y + w.z * x.z + w.w * x.w;
        }
#pragma unroll
        for (int o = 8; o; o >>= 1) acc += __shfl_down_sync(0xffffffffu, acc, o, 16);
        if (lane == 0) dst[r] = acc;
    }
}

__global__ void __launch_bounds__(NT, 1)
controller_kernel(const float* __restrict__ emb,   const float* __restrict__ w_ih,
                  const float* __restrict__ w_hh,  const float* __restrict__ b_ih,
                  const float* __restrict__ b_hh,  const float* __restrict__ w1,
                  const float* __restrict__ w2,    const float* __restrict__ idxfc,
                  const float* __restrict__ opfc,  float* __restrict__ out) {
    extern __shared__ __align__(16) float smraw[];
    SM* s = (SM*)smraw;
    const int tid = threadIdx.x;
    const int b   = blockIdx.x;

    // ---------------- setup: stage weights into SMEM ----------------
    for (int i = tid; i < 32 * 1024; i += NT) {
        int row = i >> 10, k = i & 1023;
        int gate = row >> 3, jj = row & 7;
        int grow = gate * 512 + b * 8 + jj;
        s->W[i] = (k < 512) ? w_ih[grow * 512 + k] : w_hh[grow * 512 + (k - 512)];
    }
    for (int i = tid; i < 8 * 512; i += NT) {
        int r = i >> 9, k = i & 511;
        s->A1[i] = w1[(b * 8 + r) * 512 + k];
        s->A2[i] = w2[(b * 8 + r) * 512 + k];
    }
    for (int i = tid; i < OPSN * 512; i += NT) s->OPF[i] = opfc[i];
    if (tid < 32) {
        int gate = tid >> 3, jj = tid & 7;
        int grow = gate * 512 + b * 8 + jj;
        s->bias[tid] = b_ih[grow] + b_hh[grow];
    }
    if (tid < 8) {
        s->idxfc8[tid] = idxfc[b * 8 + tid];
        s->cslice[tid] = 0.f;
        gAnchors[b * 8 + tid] = 0.f;              // anchors[0] = zeros
    }
    if (tid < LP1 * 8) s->anchW1loc[tid] = 0.f;
    if (tid < D) { s->xbuf[tid] = emb[OPSN * D + tid]; s->hfull[tid] = 0.f; }
    if (tid == 0) {
        s->keyw[0] = 0u; s->keyw[1] = 42u;        // jax.random.key(42)
        s->lpSum = 0.f; s->entSum = 0.f;
    }
    __syncthreads();

    // ---------------- initial construct_node: cell(emb[16], 0, 0) -----------
    cell_phase(s, tid, b, gHb);
    gbar(tid);
    if (tid < D) s->hfull[tid] = gHb[tid];
    __syncthreads();
    attn_dot(s->A1, s->hfull, &s->anchW1loc[0], tid);   // anchors_w1[0]

    // ---------------- main loop: 32 steps, 3 grid barriers each -------------
    for (int t = 0; t < NSTEP; t++) {
        __syncthreads();   // xbuf / anchW1loc / key from previous step visible

        // phase 1: cell1 (h,c <- cell(inp, h, c))  -> gHa
        cell_phase(s, tid, b, gHa);
        gbar(tid);

        // phase 2: attention partials over owned dims
        if (tid < D) s->hfull[tid] = gHa[tid];
        __syncthreads();
        attn_dot(s->A2, s->hfull, s->hw2s, tid);
        __syncthreads();
        if (tid < LP1) {
            float p = 0.f;
#pragma unroll
            for (int r = 0; r < 8; r++)
                p += tanhf(s->anchW1loc[tid * 8 + r] + s->hw2s[r]) * s->idxfc8[r];
            gPart[tid * GRID + b] = p;
        }
        gbar(tid);

        // phase 3: node logits (replicated, fixed order), sample, cell2
        if (tid < 3) {   // jax.random.split(key, 3), partitionable
            unsigned o0, o1;
            tf2x32(s->keyw[0], s->keyw[1], 0u, (unsigned)tid, o0, o1);
            s->split6[2 * tid] = o0; s->split6[2 * tid + 1] = o1;
        }
        if (tid < LP1) {
            float v = 0.f;
            for (int bb = 0; bb < GRID; bb++) v += gPart[tid * GRID + bb];
            v = 2.5f * tanhf(v * 0.2f);           // TANH_C * tanh(x / TEMP)
            if (tid > t) v = -1e9f;               // mask invalid anchors
            s->vals[tid] = v;
        }
        __syncthreads();
        if (tid < LP1) {
            unsigned o0, o1;
            tf2x32(s->split6[0], s->split6[1], 0u, (unsigned)tid, o0, o1);
            s->draws[tid] = s->vals[tid] + gumbelf(o0 ^ o1);
        }
        __syncthreads();
        if (tid == 0) {
            int best = 0; float bv = s->draws[0];
            for (int a = 1; a < LP1; a++)
                if (s->draws[a] > bv) { bv = s->draws[a]; best = a; }
            s->nodeIdx = best;
            float m = s->vals[0];
            for (int a = 1; a < LP1; a++) m = fmaxf(m, s->vals[a]);
            float se = 0.f;
            for (int a = 0; a < LP1; a++) se += expf(s->vals[a] - m);
            float lse = logf(se);
            s->nodeLp = -(s->vals[best] - m - lse);
            float ent = 0.f;
            for (int a = 0; a <= t; a++) {
                float l = s->vals[a] - m - lse;
                ent -= l * expf(l);
            }
            s->nodeEnt = ent;
        }
        __syncthreads();
        if (tid < D) s->xbuf[tid] = gAnchors[s->nodeIdx * D + tid];
        __syncthreads();
        cell_phase(s, tid, b, gHb);               // cell2 -> gHb
        gbar(tid);

        // phase 4: op head, sample, state updates (no barrier: double-buffered)
        if (tid < D) s->hfull[tid] = gHb[tid];
        __syncthreads();
        {
            int o = tid >> 5, lane = tid & 31;    // 16 ops x 32 lanes x 16 elems
            const float4* mp = (const float4*)&s->OPF[o * 512 + lane * 16];
            const float4* vp = (const float4*)&s->hfull[lane * 16];
            float acc = 0.f;
#pragma unroll
            for (int i = 0; i < 4; i++) {
                float4 w = mp[i], x = vp[i];
                acc += w.x * x.x + w.y * x.y + w.z * x.z + w.w * x.w;
            }
#pragma unroll
            for (int off = 16; off; off >>= 1)
                acc += __shfl_down_sync(0xffffffffu, acc, off);
            if (lane == 0) s->vals[o] = tanhf(acc * 0.2f);  // (C/RED)=1.0
        }
        __syncthreads();
        if (tid < OPSN) {
            unsigned o0, o1;
            tf2x32(s->split6[2], s->split6[3], 0u, (unsigned)tid, o0, o1);
            s->draws[tid] = s->vals[tid] + gumbelf(o0 ^ o1);
        }
        __syncthreads();
        if (tid == 0) {
            int best = 0; float bv = s->draws[0];
            for (int o = 1; o < OPSN; o++)
                if (s->draws[o] > bv) { bv = s->draws[o]; best = o; }
            s->opIdx = best;
            float m = s->vals[0];
            for (int o = 1; o < OPSN; o++) m = fmaxf(m, s->vals[o]);
            float se = 0.f;
            for (int o = 0; o < OPSN; o++) se += expf(s->vals[o] - m);
            float lse = logf(se);
            float opLp = -(s->vals[best] - m - lse);
            float ent = 0.f;
            for (int o = 0; o < OPSN; o++) {
                float l = s->vals[o] - m - lse;
                ent -= l * expf(l);
            }
            s->lpSum  += s->nodeLp + opLp;
            s->entSum += s->nodeEnt + ent;
            s->keyw[0] = s->split6[4]; s->keyw[1] = s->split6[5];  // carry key
            if (b == 0) {
                out[2 * t]     = (float)s->nodeIdx;
                out[2 * t + 1] = (float)s->opIdx;
            }
        }
        __syncthreads();
        if (tid < 8) gAnchors[(t + 1) * D + b * 8 + tid] = s->hfull[b * 8 + tid];
        attn_dot(s->A1, s->hfull, &s->anchW1loc[(t + 1) * 8], tid);
        if (tid < D) s->xbuf[tid] = emb[s->opIdx * D + tid];
    }

    if (b == 0 && tid == 0) { out[64] = s->entSum; out[65] = s->lpSum; }
}

extern "C" void kernel_launch(void* const* d_in, const int* in_sizes, int n_in,
                              void* d_out, int out_size) {
    (void)in_sizes; (void)n_in; (void)out_size;
    cudaFuncSetAttribute(controller_kernel,
                         cudaFuncAttributeMaxDynamicSharedMemorySize,
                         (int)sizeof(SM));
    controller_kernel<<<GRID, NT, sizeof(SM)>>>(
        (const float*)d_in[0],  // embedding
        (const float*)d_in[1],  // w_ih
        (const float*)d_in[2],  // w_hh
        (const float*)d_in[3],  // b_ih
        (const float*)d_in[4],  // b_hh
        (const float*)d_in[5],  // w_attn_1
        (const float*)d_in[6],  // w_attn_2
        (const float*)d_in[7],  // index_fc
        (const float*)d_in[8],  // op_fc
        (float*)d_out);
}

// round 8
// speedup vs baseline: 2.0273x; 2.0273x over previous
#include <cuda_runtime.h>
#include <cstdint>

// ============================================================================
// NAS LSTM controller, 32 sequential steps, single persistent kernel.
// 64 CTAs x 512 threads. Weights resident in SMEM, conflict-free access.
// All-report grid barrier (release/acquire epoch flags, no contended atomic).
// Exact JAX threefry2x32 sampling replicated per CTA (deterministic).
// ============================================================================

#define GRID  64
#define NT    512
#define D     512
#define LP1   33
#define NSTEP 32
#define OPSN  16

// ------------------------------ global state -------------------------------
__device__ float    gHa[D];
__device__ float    gHb[D];
__device__ float    gAnchors[LP1 * D];
__device__ float    gPart[LP1 * GRID];
__device__ unsigned gFlags[GRID];          // monotonic per-CTA barrier epochs

// ------------------------------ shared layout ------------------------------
struct SM {
    float W[32 * 1024];        // 32 gate rows: [w_ih row | w_hh row]  128 KB
    float A1[8 * D];           // 16 KB
    float A2[8 * D];           // 16 KB
    float OPF[OPSN * D];       // 32 KB
    float vec[2 * D];          // [x | h]
    float bias[32];
    float gbuf[32];
    float idxfc8[8];
    float hw2s[8];
    float anchW1loc[LP1 * 8];
    float cslice[8];
    float vals[40];
    float draws[40];
    float ework[40];
    float m_sh;
    unsigned keyw[2];
    unsigned split6[6];
    int   nodeIdx;
    int   opIdx;
    float nodeLp, nodeEnt;
    float lpSum, entSum;
};

// --------------------------- release/acquire ops ---------------------------
__device__ __forceinline__ unsigned ldacq(const unsigned* p) {
    unsigned v;
    asm volatile("ld.acquire.gpu.global.u32 %0, [%1];" : "=r"(v) : "l"(p) : "memory");
    return v;
}
__device__ __forceinline__ void strel(unsigned* p, unsigned v) {
    asm volatile("st.release.gpu.global.u32 [%0], %1;" :: "l"(p), "r"(v) : "memory");
}

// All-report grid barrier: each CTA publishes its epoch; 64 threads poll all
// slots. Monotonic counters -> safe across barriers and graph replays.
__device__ __forceinline__ void gbar(int tid, int b, unsigned& ep) {
    ep++;
    __syncthreads();
    if (tid == 0) strel(&gFlags[b], ep);
    if (tid < GRID) {
        while (ldacq(&gFlags[tid]) < ep) { }
    }
    __syncthreads();
}

// ------------------------------ threefry2x32 -------------------------------
__device__ __forceinline__ void tf2x32(unsigned k0, unsigned k1,
                                       unsigned x0, unsigned x1,
                                       unsigned& o0, unsigned& o1) {
    unsigned ks2 = k0 ^ k1 ^ 0x1BD11BDAu;
    x0 += k0; x1 += k1;
#define TFR(r) { x0 += x1; x1 = (x1 << (r)) | (x1 >> (32 - (r))); x1 ^= x0; }
    TFR(13) TFR(15) TFR(26) TFR(6)   x0 += k1;  x1 += ks2 + 1u;
    TFR(17) TFR(29) TFR(16) TFR(24)  x0 += ks2; x1 += k0 + 2u;
    TFR(13) TFR(15) TFR(26) TFR(6)   x0 += k0;  x1 += k1 + 3u;
    TFR(17) TFR(29) TFR(16) TFR(24)  x0 += k1;  x1 += ks2 + 4u;
    TFR(13) TFR(15) TFR(26) TFR(6)   x0 += ks2; x1 += k0 + 5u;
#undef TFR
    o0 = x0; o1 = x1;
}

__device__ __forceinline__ float gumbelf(unsigned bits) {
    float f = __uint_as_float((bits >> 9) | 0x3f800000u) - 1.0f;
    const float tiny = 1.17549435e-38f;
    float u = fmaxf(tiny, f * (1.0f - tiny) + tiny);
    return -logf(-logf(u));
}

__device__ __forceinline__ float sigf(float x) {
    return 1.0f / (1.0f + expf(-x));
}

// LSTM cell: 32 gate rows x 16 lanes, conflict-free lane-contiguous chunks.
__device__ __forceinline__ void cell_phase(SM* s, int tid, int b, float* gout) {
    int row = tid >> 4, lane = tid & 15;
    const float4* wp = (const float4*)&s->W[row * 1024];
    const float4* vp = (const float4*)s->vec;
    float acc = 0.f;
#pragma unroll
    for (int i = 0; i < 16; i++) {
        float4 w = wp[i * 16 + lane], v = vp[i * 16 + lane];
        acc += w.x * v.x + w.y * v.y + w.z * v.z + w.w * v.w;
    }
#pragma unroll
    for (int o = 8; o; o >>= 1) acc += __shfl_down_sync(0xffffffffu, acc, o, 16);
    if (lane == 0) s->gbuf[row] = acc + s->bias[row];
    __syncthreads();
    if (tid < 8) {
        float gi = s->gbuf[tid],      gf = s->gbuf[8 + tid];
        float gg = s->gbuf[16 + tid], go = s->gbuf[24 + tid];
        float c2 = sigf(gf) * s->cslice[tid] + sigf(gi) * tanhf(gg);
        float h2 = sigf(go) * tanhf(c2);
        s->cslice[tid] = c2;
        gout[b * 8 + tid] = h2;
    }
}

// 8 dots of an 8x512 matrix slice with v (threads 0..127), conflict-free.
__device__ __forceinline__ void attn_dot(const float* M, const float* v,
                                         float* dst, int tid) {
    if (tid < 128) {
        int r = tid >> 4, lane = tid & 15;
        const float4* mp = (const float4*)&M[r * 512];
        const float4* vp = (const float4*)v;
        float acc = 0.f;
#pragma unroll
        for (int i = 0; i < 8; i++) {
            float4 w = mp[i * 16 + lane], x = vp[i * 16 + lane];
            acc += w.x * x.x + w.y * x.y + w.z * x.z + w.w * x.w;
        }
#pragma unroll
        for (int o = 8; o; o >>= 1) acc += __shfl_down_sync(0xffffffffu, acc, o, 16);
        if (lane == 0) dst[r] = acc;
    }
}

__global__ void __launch_bounds__(NT, 1)
controller_kernel(const float* __restrict__ emb,   const float* __restrict__ w_ih,
                  const float* __restrict__ w_hh,  const float* __restrict__ b_ih,
                  const float* __restrict__ b_hh,  const float* __restrict__ w1,
                  const float* __restrict__ w2,    const float* __restrict__ idxfc,
                  const float* __restrict__ opfc,  float* __restrict__ out) {
    extern __shared__ __align__(16) float smraw[];
    SM* s = (SM*)smraw;
    const int tid = threadIdx.x;
    const int b   = blockIdx.x;
    unsigned ep = ldacq(&gFlags[b]);   // epoch base (equal across CTAs)

    // ---------------- stage weights into SMEM ----------------
    for (int i = tid; i < 32 * 1024; i += NT) {
        int row = i >> 10, k = i & 1023;
        int gate = row >> 3, jj = row & 7;
        int grow = gate * 512 + b * 8 + jj;
        s->W[i] = (k < 512) ? w_ih[grow * 512 + k] : w_hh[grow * 512 + (k - 512)];
    }
    for (int i = tid; i < 8 * 512; i += NT) {
        int r = i >> 9, k = i & 511;
        s->A1[i] = w1[(b * 8 + r) * 512 + k];
        s->A2[i] = w2[(b * 8 + r) * 512 + k];
    }
    for (int i = tid; i < OPSN * 512; i += NT) s->OPF[i] = opfc[i];
    if (tid < 32) {
        int gate = tid >> 3, jj = tid & 7;
        int grow = gate * 512 + b * 8 + jj;
        s->bias[tid] = b_ih[grow] + b_hh[grow];
    }
    if (tid < 8) {
        s->idxfc8[tid] = idxfc[b * 8 + tid];
        s->cslice[tid] = 0.f;
        gAnchors[b * 8 + tid] = 0.f;
    }
    if (tid < LP1 * 8) s->anchW1loc[tid] = 0.f;
    if (tid < D) { s->vec[tid] = emb[OPSN * D + tid]; s->vec[D + tid] = 0.f; }
    if (tid == 0) {
        s->keyw[0] = 0u; s->keyw[1] = 42u;
        s->lpSum = 0.f; s->entSum = 0.f;
    }
    __syncthreads();

    // ---------------- initial construct_node ----------------
    cell_phase(s, tid, b, gHb);
    gbar(tid, b, ep);
    if (tid < D) s->vec[D + tid] = __ldcg(&gHb[tid]);
    __syncthreads();
    attn_dot(s->A1, &s->vec[D], &s->anchW1loc[0], tid);

    // ---------------- main loop: 3 grid barriers per step ----------------
    for (int t = 0; t < NSTEP; t++) {
        __syncthreads();

        // phase 1: cell1 -> gHa
        cell_phase(s, tid, b, gHa);
        gbar(tid, b, ep);

        // phase 2: attention partials over owned dims
        if (tid < D) s->vec[D + tid] = __ldcg(&gHa[tid]);
        __syncthreads();
        attn_dot(s->A2, &s->vec[D], s->hw2s, tid);
        __syncthreads();
        if (tid < LP1) {
            float p = 0.f;
#pragma unroll
            for (int r = 0; r < 8; r++)
                p += tanhf(s->anchW1loc[tid * 8 + r] + s->hw2s[r]) * s->idxfc8[r];
            gPart[tid * GRID + b] = p;
        }
        gbar(tid, b, ep);

        // phase 3: node logits (replicated fixed order), sample, cell2
        if (tid < 3) {
            unsigned o0, o1;
            tf2x32(s->keyw[0], s->keyw[1], 0u, (unsigned)tid, o0, o1);
            s->split6[2 * tid] = o0; s->split6[2 * tid + 1] = o1;
        }
        if (tid < LP1) {
            const float4* pp = (const float4*)&gPart[tid * GRID];
            float v = 0.f;
#pragma unroll
            for (int i = 0; i < GRID / 4; i++) {
                float4 p = __ldcg(&pp[i]);
                v += p.x; v += p.y; v += p.z; v += p.w;
            }
            v = 2.5f * tanhf(v * 0.2f);
            if (tid > t) v = -1e9f;
            s->vals[tid] = v;
            unsigned o0, o1;
            tf2x32(s->split6[0], s->split6[1], 0u, (unsigned)tid, o0, o1);
            s->draws[tid] = v + gumbelf(o0 ^ o1);
        }
        __syncthreads();
        if (tid == 0) {
            int best = 0; float bv = s->draws[0];
            float m = s->vals[0];
            for (int a = 1; a < LP1; a++) {
                if (s->draws[a] > bv) { bv = s->draws[a]; best = a; }
                m = fmaxf(m, s->vals[a]);
            }
            s->nodeIdx = best; s->m_sh = m;
        }
        __syncthreads();
        if (tid < LP1) s->ework[tid] = expf(s->vals[tid] - s->m_sh);
        if (tid < D) s->vec[tid] = __ldcg(&gAnchors[s->nodeIdx * D + tid]);
        __syncthreads();
        if (tid == 0) {
            float se = 0.f;
            for (int a = 0; a < LP1; a++) se += s->ework[a];
            float lse = logf(se), inv = 1.0f / se, m = s->m_sh;
            s->nodeLp = -(s->vals[s->nodeIdx] - m - lse);
            float ent = 0.f;
            for (int a = 0; a <= t; a++) {
                float l = s->vals[a] - m - lse;
                ent -= l * (s->ework[a] * inv);
            }
            s->nodeEnt = ent;
        }
        __syncthreads();
        cell_phase(s, tid, b, gHb);
        gbar(tid, b, ep);

        // phase 4: op head, sample, state updates (no barrier needed)
        if (tid < D) s->vec[D + tid] = __ldcg(&gHb[tid]);
        __syncthreads();
        {
            int o = tid >> 5, lane = tid & 31;
            const float4* mp = (const float4*)&s->OPF[o * 512];
            const float4* vp = (const float4*)&s->vec[D];
            float acc = 0.f;
#pragma unroll
            for (int i = 0; i < 4; i++) {
                float4 w = mp[i * 32 + lane], x = vp[i * 32 + lane];
                acc += w.x * x.x + w.y * x.y + w.z * x.z + w.w * x.w;
            }
#pragma unroll
            for (int off = 16; off; off >>= 1)
                acc += __shfl_down_sync(0xffffffffu, acc, off);
            if (lane == 0) s->vals[o] = tanhf(acc * 0.2f);
        }
        __syncthreads();
        if (tid < OPSN) {
            unsigned o0, o1;
            tf2x32(s->split6[2], s->split6[3], 0u, (unsigned)tid, o0, o1);
            s->draws[tid] = s->vals[tid] + gumbelf(o0 ^ o1);
        }
        __syncthreads();
        if (tid == 0) {
            int best = 0; float bv = s->draws[0];
            float m = s->vals[0];
            for (int o = 1; o < OPSN; o++) {
                if (s->draws[o] > bv) { bv = s->draws[o]; best = o; }
                m = fmaxf(m, s->vals[o]);
            }
            s->opIdx = best; s->m_sh = m;
        }
        __syncthreads();
        if (tid < OPSN) s->ework[tid] = expf(s->vals[tid] - s->m_sh);
        __syncthreads();
        if (tid == 0) {
            float se = 0.f;
            for (int o = 0; o < OPSN; o++) se += s->ework[o];
            float lse = logf(se), inv = 1.0f / se, m = s->m_sh;
            float opLp = -(s->vals[s->opIdx] - m - lse);
            float ent = 0.f;
            for (int o = 0; o < OPSN; o++) {
                float l = s->vals[o] - m - lse;
                ent -= l * (s->ework[o] * inv);
            }
            s->lpSum  += s->nodeLp + opLp;
            s->entSum += s->nodeEnt + ent;
            s->keyw[0] = s->split6[4]; s->keyw[1] = s->split6[5];
            if (b == 0) {
                out[2 * t]     = (float)s->nodeIdx;
                out[2 * t + 1] = (float)s->opIdx;
            }
        }
        __syncthreads();
        if (tid < 8) gAnchors[(t + 1) * D + b * 8 + tid] = s->vec[D + b * 8 + tid];
        attn_dot(s->A1, &s->vec[D], &s->anchW1loc[(t + 1) * 8], tid);
        if (tid >= 128 && tid < 128 + D) { }   // (no-op, keeps divergence simple)
        if (tid < D) { }                       // xbuf written below after sync-free ok
        if (tid < D) s->vec[tid] = emb[s->opIdx * D + tid];
    }

    if (b == 0 && tid == 0) { out[64] = s->entSum; out[65] = s->lpSum; }
}

extern "C" void kernel_launch(void* const* d_in, const int* in_sizes, int n_in,
                              void* d_out, int out_size) {
    (void)in_sizes; (void)n_in; (void)out_size;
    cudaFuncSetAttribute(controller_kernel,
                         cudaFuncAttributeMaxDynamicSharedMemorySize,
                         (int)sizeof(SM));
    controller_kernel<<<GRID, NT, sizeof(SM)>>>(
        (const float*)d_in[0],  // embedding
        (const float*)d_in[1],  // w_ih
        (const float*)d_in[2],  // w_hh
        (const float*)d_in[3],  // b_ih
        (const float*)d_in[4],  // b_hh
        (const float*)d_in[5],  // w_attn_1
        (const float*)d_in[6],  // w_attn_2
        (const float*)d_in[7],  // index_fc
        (const float*)d_in[8],  // op_fc
        (float*)d_out);
}

// round 11
// speedup vs baseline: 2.1533x; 1.0622x over previous
#include <cuda_runtime.h>
#include <cstdint>

// ============================================================================
// NAS LSTM controller, 32 sequential steps, single persistent kernel.
// 64 CTAs x 512 threads. All weights in SMEM. Cross-CTA communication via
// epoch-tagged 64-bit words (tag<<32 | float bits) with relaxed gpu-scope
// atomics: barrier and data merged into one L2 round trip per phase.
// Cells use h-only matvecs; x-gate contributions come from lookup tables
// (embGates precomputed, anchGates built incrementally). All threefry keys
// and gumbels precomputed at setup (key chain is data-independent).
// ============================================================================

#define GRID  64
#define NT    512
#define D     512
#define LP1   33
#define NSTEP 32
#define OPSN  16

// ------------------------------ global state -------------------------------
__device__ unsigned long long gPub1[GRID * 520];  // [b][0..511]=attn part2, [512..519]=h1 slice
__device__ unsigned long long gPub2[LP1 * GRID];  // [a][b] node-logit partials
__device__ unsigned long long gPub3[GRID * 24];   // [b][0..7]=h2 slice, [8..23]=op partials
__device__ unsigned gEpochBase;

// ------------------------------ shared layout ------------------------------
struct __align__(16) SM {
    float Whh[32 * 512];       // 64 KB   [row][k], row = gate*8 + jj
    float Wih[32 * 512];       // 64 KB
    float A1[8 * 512];         // 16 KB   own rows of w_attn_1, row-major
    float A2T[8 * 512];        // 16 KB   [j][r]: w_attn_2[r][own dim j]
    float hprev[512];          // h into cell1 (prev h2)
    float h1full[512];
    float embG[17 * 32];       // x-gates (incl bias) for each embedding
    float anchG[LP1 * 32];     // x-gates (incl bias) for each anchor
    float anchW1[LP1 * 8];     // own slice of anchors_w1
    float OPFT[OPSN * 8];      // op_fc[:, own 8 dims]
    float idxfc8[8];
    float bias[32];
    float cslice[8];
    float gbuf[32];
    float hw2s[8];
    float warpPart[16 * 8];
    float plogPart[LP1 * 8];
    float sumPart[LP1 * 8];
    float vals[36];
    float oplog[16];
    float gnode[NSTEP * LP1];  // precomputed gumbels
    float gop[NSTEP * OPSN];
    unsigned keys2[NSTEP * 2];
    int   nodeIdx, opIdx, sel;
    float nodeLp, nodeEnt, opLp, opEnt;
    float lpSum, entSum;
    unsigned base;
};

// ------------------------- tagged publish / poll ---------------------------
__device__ __forceinline__ void pub64(unsigned long long* p, float v, unsigned tag) {
    unsigned long long w = ((unsigned long long)tag << 32) | (unsigned long long)__float_as_uint(v);
    asm volatile("st.relaxed.gpu.global.u64 [%0], %1;" :: "l"(p), "l"(w) : "memory");
}
__device__ __forceinline__ float poll64(const unsigned long long* p, unsigned tag) {
    unsigned long long w;
    do {
        asm volatile("ld.relaxed.gpu.global.u64 %0, [%1];" : "=l"(w) : "l"(p) : "memory");
    } while ((unsigned)(w >> 32) != tag);
    return __uint_as_float((unsigned)w);
}

// ------------------------------ threefry2x32 -------------------------------
__device__ __forceinline__ void tf2x32(unsigned k0, unsigned k1,
                                       unsigned x0, unsigned x1,
                                       unsigned& o0, unsigned& o1) {
    unsigned ks2 = k0 ^ k1 ^ 0x1BD11BDAu;
    x0 += k0; x1 += k1;
#define TFR(r) { x0 += x1; x1 = (x1 << (r)) | (x1 >> (32 - (r))); x1 ^= x0; }
    TFR(13) TFR(15) TFR(26) TFR(6)   x0 += k1;  x1 += ks2 + 1u;
    TFR(17) TFR(29) TFR(16) TFR(24)  x0 += ks2; x1 += k0 + 2u;
    TFR(13) TFR(15) TFR(26) TFR(6)   x0 += k0;  x1 += k1 + 3u;
    TFR(17) TFR(29) TFR(16) TFR(24)  x0 += k1;  x1 += ks2 + 4u;
    TFR(13) TFR(15) TFR(26) TFR(6)   x0 += ks2; x1 += k0 + 5u;
#undef TFR
    o0 = x0; o1 = x1;
}

__device__ __forceinline__ float gumbelf(unsigned bits) {
    float f = __uint_as_float((bits >> 9) | 0x3f800000u) - 1.0f;
    const float tiny = 1.17549435e-38f;
    float u = fmaxf(tiny, f * (1.0f - tiny) + tiny);
    return -logf(-logf(u));
}

__device__ __forceinline__ float sigf(float x) { return 1.0f / (1.0f + expf(-x)); }

// ----------------- LSTM cell: gates = Whh*hin + xc; update c,h -------------
__device__ __forceinline__ void cell_hh(SM* s, const float* hin, const float* xc,
                                        int tid, float* houtOwn) {
    int row = tid >> 4, lane = tid & 15;
    const float4* wp = (const float4*)&s->Whh[row * 512];
    const float4* vp = (const float4*)hin;
    float acc = 0.f;
#pragma unroll
    for (int i = 0; i < 8; i++) {
        float4 w = wp[i * 16 + lane], v = vp[i * 16 + lane];
        acc += w.x * v.x + w.y * v.y + w.z * v.z + w.w * v.w;
    }
#pragma unroll
    for (int o = 8; o; o >>= 1) acc += __shfl_down_sync(0xffffffffu, acc, o, 16);
    if (lane == 0) s->gbuf[row] = acc + xc[row];
    __syncthreads();
    if (tid < 8) {
        float gi = s->gbuf[tid],      gf = s->gbuf[8 + tid];
        float gg = s->gbuf[16 + tid], go = s->gbuf[24 + tid];
        float c2 = sigf(gf) * s->cslice[tid] + sigf(gi) * tanhf(gg);
        float h2 = sigf(go) * tanhf(c2);
        s->cslice[tid] = c2;
        houtOwn[tid] = h2;
    }
    __syncthreads();
}

// 8 dots of an 8x512 smem matrix with v (threads 0..127), conflict-free.
__device__ __forceinline__ void attn_dot(const float* M, const float* v,
                                         float* dst, int tid) {
    if (tid < 128) {
        int r = tid >> 4, lane = tid & 15;
        const float4* mp = (const float4*)&M[r * 512];
        const float4* vp = (const float4*)v;
        float acc = 0.f;
#pragma unroll
        for (int i = 0; i < 8; i++) {
            float4 w = mp[i * 16 + lane], x = vp[i * 16 + lane];
            acc += w.x * x.x + w.y * x.y + w.z * x.z + w.w * x.w;
        }
#pragma unroll
        for (int o = 8; o; o >>= 1) acc += __shfl_down_sync(0xffffffffu, acc, o, 16);
        if (lane == 0) dst[r] = acc;
    }
}

// ----- warp-parallel categorical sample + lp + entropy (tid<32 only) -------
// vals: n logits (masked entries already -1e9); g: n gumbels.
__device__ __forceinline__ void warp_sample(const float* vals, const float* g, int n,
                                            int* oIdx, float* oLp, float* oEnt, int lane) {
    const float NINF = __int_as_float(0xff800000);
    float v1 = (lane < n) ? vals[lane] : NINF;
    float d1 = (lane < n) ? v1 + g[lane] : NINF;
    int   i1 = lane;
    float v2 = NINF;
    if (lane == 0 && n > 32) {
        v2 = vals[32];
        float d2 = v2 + g[32];
        if (d2 > d1) { d1 = d2; i1 = 32; }
    }
#pragma unroll
    for (int off = 16; off; off >>= 1) {
        float dv = __shfl_down_sync(0xffffffffu, d1, off);
        int   di = __shfl_down_sync(0xffffffffu, i1, off);
        if (dv > d1 || (dv == d1 && di < i1)) { d1 = dv; i1 = di; }
    }
    int best = __shfl_sync(0xffffffffu, i1, 0);
    float m1 = (lane < n) ? v1 : NINF;
    if (lane == 0 && n > 32) m1 = fmaxf(m1, v2);
#pragma unroll
    for (int off = 16; off; off >>= 1) m1 = fmaxf(m1, __shfl_xor_sync(0xffffffffu, m1, off));
    float se = (lane < n) ? expf(v1 - m1) : 0.f;
    if (lane == 0 && n > 32) se += expf(v2 - m1);
#pragma unroll
    for (int off = 16; off; off >>= 1) se += __shfl_xor_sync(0xffffffffu, se, off);
    float lse = logf(se);
    float ent = 0.f;
    if (lane < n)            { float l = v1 - m1 - lse; ent -= l * expf(l); }
    if (lane == 0 && n > 32) { float l = v2 - m1 - lse; ent -= l * expf(l); }
#pragma unroll
    for (int off = 16; off; off >>= 1) ent += __shfl_xor_sync(0xffffffffu, ent, off);
    if (lane == 0) {
        *oIdx = best;
        *oLp  = -(vals[best] - m1 - lse);
        *oEnt = ent;
    }
}

__global__ void __launch_bounds__(NT, 1)
controller_kernel(const float* __restrict__ emb,   const float* __restrict__ w_ih,
                  const float* __restrict__ w_hh,  const float* __restrict__ b_ih,
                  const float* __restrict__ b_hh,  const float* __restrict__ w1,
                  const float* __restrict__ w2,    const float* __restrict__ idxfc,
                  const float* __restrict__ opfc,  float* __restrict__ out) {
    extern __shared__ __align__(16) float smraw[];
    SM* s = (SM*)smraw;
    const int tid = threadIdx.x;
    const int b   = blockIdx.x;

    // ---------------- setup: stage weights ----------------
    if (tid == 0) {
        s->base = *(volatile unsigned*)&gEpochBase;
        s->sel = OPSN;                 // sentinel embedding
        s->lpSum = 0.f; s->entSum = 0.f;
    }
    for (int i = tid; i < 32 * 512; i += NT) {
        int row = i >> 9, k = i & 511;
        int gate = row >> 3, jj = row & 7;
        int grow = gate * 512 + b * 8 + jj;
        s->Whh[i] = w_hh[grow * 512 + k];
        s->Wih[i] = w_ih[grow * 512 + k];
    }
    for (int i = tid; i < 8 * 512; i += NT) {
        int a = i >> 9, k = i & 511;
        s->A1[i]  = w1[(b * 8 + a) * 512 + k];
        s->A2T[i] = w2[k * 512 + b * 8 + a];   // [j][r]
    }
    if (tid < OPSN * 8) {
        int o = tid >> 3, j = tid & 7;
        s->OPFT[tid] = opfc[o * 512 + b * 8 + j];
    }
    if (tid < 32) {
        int gate = tid >> 3, jj = tid & 7;
        int grow = gate * 512 + b * 8 + jj;
        float bb = b_ih[grow] + b_hh[grow];
        s->bias[tid]  = bb;
        s->anchG[tid] = bb;            // anchor 0 = zeros -> x-gates = bias
    }
    if (tid < 8) { s->idxfc8[tid] = idxfc[b * 8 + tid]; s->cslice[tid] = 0.f; }
    __syncthreads();

    // embGates: x @ w_ih.T + bias for all 17 embeddings
    {
        int row = tid >> 4, lane = tid & 15;
        const float4* wr = (const float4*)&s->Wih[row * 512];
        for (int e = 0; e < 17; e++) {
            const float4* er = (const float4*)&emb[e * 512];
            float acc = 0.f;
#pragma unroll
            for (int i = 0; i < 8; i++) {
                float4 w = wr[i * 16 + lane];
                float4 v = __ldg(&er[i * 16 + lane]);
                acc += w.x * v.x + w.y * v.y + w.z * v.z + w.w * v.w;
            }
#pragma unroll
            for (int o = 8; o; o >>= 1) acc += __shfl_down_sync(0xffffffffu, acc, o, 16);
            if (lane == 0) s->embG[e * 32 + row] = acc + s->bias[row];
        }
    }
    // key chain (data-independent): key_{t+1} = split(key_t,3)[2]
    if (tid == 0) {
        unsigned k0 = 0u, k1 = 42u;
        for (int t = 0; t < NSTEP; t++) {
            s->keys2[2 * t] = k0; s->keys2[2 * t + 1] = k1;
            unsigned o0, o1; tf2x32(k0, k1, 0u, 2u, o0, o1);
            k0 = o0; k1 = o1;
        }
    }
    __syncthreads();
    // all gumbels precomputed
    for (int p = tid; p < NSTEP * (LP1 + OPSN); p += NT) {
        int t = p / (LP1 + OPSN), r = p % (LP1 + OPSN);
        unsigned K0 = s->keys2[2 * t], K1 = s->keys2[2 * t + 1];
        unsigned c0, c1, o0, o1;
        if (r < LP1) {
            tf2x32(K0, K1, 0u, 0u, c0, c1);
            tf2x32(c0, c1, 0u, (unsigned)r, o0, o1);
            s->gnode[t * LP1 + r] = gumbelf(o0 ^ o1);
        } else {
            int o = r - LP1;
            tf2x32(K0, K1, 0u, 1u, c0, c1);
            tf2x32(c0, c1, 0u, (unsigned)o, o0, o1);
            s->gop[t * OPSN + o] = gumbelf(o0 ^ o1);
        }
    }
    __syncthreads();
    const unsigned base = s->base;

    // ---------------- initial construct_node: cell(emb[16], 0, 0) -----------
    if (tid < 8) {
        float gi = s->embG[16 * 32 + tid],      gf = s->embG[16 * 32 + 8 + tid];
        float gg = s->embG[16 * 32 + 16 + tid], go = s->embG[16 * 32 + 24 + tid];
        (void)gf;  // f-gate * c(=0) contributes 0
        float c2 = sigf(gi) * tanhf(gg);
        float h2 = sigf(go) * tanhf(c2);
        s->cslice[tid] = c2;
        s->hprev[b * 8 + tid] = h2;
        pub64(&gPub3[b * 24 + tid], h2, base + 1);
    }
    if ((tid >> 3) != b)
        s->hprev[tid] = poll64(&gPub3[(tid >> 3) * 24 + (tid & 7)], base + 1);
    __syncthreads();
    if (b == 0 && tid == 0) *(volatile unsigned*)&gEpochBase = base + 128;

    // ---------------- main loop ----------------
    for (int t = 0; t < NSTEP; t++) {
        const unsigned tag1 = base + 2 + 3 * t;
        const unsigned tag2 = tag1 + 1;
        const unsigned tag3 = tag1 + 2;

        // cell1: h,c <- cell(emb[sel], hprev, c)
        cell_hh(s, s->hprev, &s->embG[s->sel * 32], tid, &s->h1full[b * 8]);

        // attention partial column from local h1 slice; publish with h1 slice
        {
            float acc = 0.f;
#pragma unroll
            for (int j = 0; j < 8; j++)
                acc += s->A2T[j * 512 + tid] * s->h1full[b * 8 + j];
            pub64(&gPub1[b * 520 + tid], acc, tag1);
            if (tid < 8) pub64(&gPub1[b * 520 + 512 + tid], s->h1full[b * 8 + tid], tag1);
        }

        // anchor-t bookkeeping from hprev (overlaps publish latency)
        if (t > 0) {
            int row = tid >> 4, lane = tid & 15;
            const float4* wp = (const float4*)&s->Wih[row * 512];
            const float4* vp = (const float4*)s->hprev;
            float acc = 0.f;
#pragma unroll
            for (int i = 0; i < 8; i++) {
                float4 w = wp[i * 16 + lane], v = vp[i * 16 + lane];
                acc += w.x * v.x + w.y * v.y + w.z * v.z + w.w * v.w;
            }
#pragma unroll
            for (int o = 8; o; o >>= 1) acc += __shfl_down_sync(0xffffffffu, acc, o, 16);
            if (lane == 0) s->anchG[t * 32 + row] = acc + s->bias[row];
        }
        attn_dot(s->A1, s->hprev, &s->anchW1[t * 8], tid);

        // consume round 1: h1 full + attn partial reduce
        if ((tid >> 3) != b)
            s->h1full[tid] = poll64(&gPub1[(tid >> 3) * 520 + 512 + (tid & 7)], tag1);
        {
            float pv = poll64(&gPub1[(tid >> 3) * 520 + b * 8 + (tid & 7)], tag1);
            pv += __shfl_down_sync(0xffffffffu, pv, 16);
            pv += __shfl_down_sync(0xffffffffu, pv, 8);
            if ((tid & 31) < 8) s->warpPart[(tid >> 5) * 8 + (tid & 7)] = pv;
        }
        __syncthreads();
        if (tid < 8) {
            float sacc = 0.f;
            for (int w = 0; w < 16; w++) sacc += s->warpPart[w * 8 + tid];
            s->hw2s[tid] = sacc;
        }
        __syncthreads();

        // node-logit partial for own 8 rows; publish
        if (tid < LP1 * 8) {
            int a = tid >> 3, rl = tid & 7;
            s->plogPart[tid] = tanhf(s->anchW1[a * 8 + rl] + s->hw2s[rl]) * s->idxfc8[rl];
        }
        __syncthreads();
        if (tid < LP1) {
            float pv = 0.f;
#pragma unroll
            for (int rl = 0; rl < 8; rl++) pv += s->plogPart[tid * 8 + rl];
            pub64(&gPub2[tid * GRID + b], pv, tag2);
        }
        // consume round 2: sum partials (ascending b), build masked logits
        if (tid < LP1 * 8) {
            int a = tid >> 3, c = tid & 7;
            float sc = 0.f;
#pragma unroll
            for (int i = 0; i < 8; i++)
                sc += poll64(&gPub2[a * GRID + c * 8 + i], tag2);
            s->sumPart[a * 8 + c] = sc;
        }
        __syncthreads();
        if (tid < LP1) {
            float v = 0.f;
#pragma unroll
            for (int c = 0; c < 8; c++) v += s->sumPart[tid * 8 + c];
            v = 2.5f * tanhf(v * 0.2f);
            if (tid > t) v = -1e9f;
            s->vals[tid] = v;
        }
        __syncthreads();
        if (tid < 32)
            warp_sample(s->vals, &s->gnode[t * LP1], LP1,
                        &s->nodeIdx, &s->nodeLp, &s->nodeEnt, tid);
        __syncthreads();

        // cell2: h,c <- cell(anchor[nodeIdx], h1, c)  (x-gates from lookup)
        cell_hh(s, s->h1full, &s->anchG[s->nodeIdx * 32], tid, &s->hprev[b * 8]);

        // publish round 3: h2 slice + op partials
        if (tid < OPSN) {
            float oa = 0.f;
#pragma unroll
            for (int j = 0; j < 8; j++)
                oa += s->OPFT[tid * 8 + j] * s->hprev[b * 8 + j];
            pub64(&gPub3[b * 24 + 8 + tid], oa, tag3);
        }
        if (tid < 8) pub64(&gPub3[b * 24 + tid], s->hprev[b * 8 + tid], tag3);

        // consume round 3
        if ((tid >> 3) != b)
            s->hprev[tid] = poll64(&gPub3[(tid >> 3) * 24 + (tid & 7)], tag3);
        {
            int o = tid >> 5, q = tid & 31;
            float p0 = poll64(&gPub3[(2 * q) * 24 + 8 + o], tag3);
            float p1 = poll64(&gPub3[(2 * q + 1) * 24 + 8 + o], tag3);
            float ps = p0 + p1;
#pragma unroll
            for (int off = 16; off; off >>= 1)
                ps += __shfl_xor_sync(0xffffffffu, ps, off);
            if (q == 0) s->oplog[o] = tanhf(ps * 0.2f);
        }
        __syncthreads();
        if (tid < 32)
            warp_sample(s->oplog, &s->gop[t * OPSN], OPSN,
                        &s->opIdx, &s->opLp, &s->opEnt, tid);
        if (tid == 0) {   // tid0 == lane0 of sampling warp: values already local
            s->lpSum  += s->nodeLp + s->opLp;
            s->entSum += s->nodeEnt + s->opEnt;
            s->sel = s->opIdx;
            if (b == 0) {
                out[2 * t]     = (float)s->nodeIdx;
                out[2 * t + 1] = (float)s->opIdx;
            }
        }
        __syncthreads();
    }

    if (b == 0 && tid == 0) { out[64] = s->entSum; out[65] = s->lpSum; }
}

extern "C" void kernel_launch(void* const* d_in, const int* in_sizes, int n_in,
                              void* d_out, int out_size) {
    (void)in_sizes; (void)n_in; (void)out_size;
    cudaFuncSetAttribute(controller_kernel,
                         cudaFuncAttributeMaxDynamicSharedMemorySize,
                         (int)sizeof(SM));
    controller_kernel<<<GRID, NT, sizeof(SM)>>>(
        (const float*)d_in[0],  // embedding
        (const float*)d_in[1],  // w_ih
        (const float*)d_in[2],  // w_hh
        (const float*)d_in[3],  // b_ih
        (const float*)d_in[4],  // b_hh
        (const float*)d_in[5],  // w_attn_1
        (const float*)d_in[6],  // w_attn_2
        (const float*)d_in[7],  // index_fc
        (const float*)d_in[8],  // op_fc
        (float*)d_out);
}

// round 12
// speedup vs baseline: 3.4166x; 1.5867x over previous
#include <cuda_runtime.h>
#include <cstdint>

// ============================================================================
// NAS LSTM controller, 32 sequential steps, single persistent kernel.
// 64 worker CTAs x 512 threads (launched as 148 CTAs; extras exit, to avoid
// the documented low-grid SM issue throttle). Weights resident in SMEM.
// Cross-CTA comm: epoch-tagged u64 words (tag<<32 | float), relaxed gpu-scope,
// consumed with batched retry-sweep polls (no serial poll chains).
// Exact JAX threefry2x32 sampling replicated per CTA (deterministic).
// ============================================================================

#define GRID   64
#define GRIDL  148
#define NT     512
#define D      512
#define LP1    33
#define NSTEP  32
#define OPSN   16

typedef unsigned long long u64t;

// ------------------------------ global state -------------------------------
__device__ u64t gPubA[GRID * 512];   // [src][dim] attn partials
__device__ u64t gPubH1[GRID * 8];    // [src][j]   h1 slices
__device__ u64t gPubI[GRID * 8];     // init h0 slices
__device__ u64t gPubL[LP1 * GRID];   // [anchor][src] node-logit partials
__device__ u64t gPubO[GRID * 24];    // [src][0..7]=h2, [8..23]=op partials
__device__ unsigned gEpochBase;

// ------------------------------ shared layout ------------------------------
struct __align__(16) SM {
    float Whh[32 * 512];       // 64 KB
    float Wih[32 * 512];       // 64 KB
    float A1[8 * 512];         // own rows of w_attn_1
    float A2T[8 * 512];        // [j][k]: w2[k][own dim j]
    float hprev[512];
    float h1full[512];
    float lsum[LP1 * 64];      // node-logit partials gathered
    float opP[OPSN * 64];
    float attnP[8 * 64];       // [own dim p][src c]
    float embG[17 * 32];       // x-gates (incl bias) per embedding
    float anchG[LP1 * 32];     // x-gates per anchor
    float anchW1[LP1 * 8];     // own slice of anchors_w1
    float OPFT[OPSN * 8];
    float gnode[NSTEP * LP1];
    float gop[NSTEP * OPSN];
    float vals[40];
    float hw2s[8];
    float idxfc8[8];
    float bias[32];
    float gbuf[32];
    float cslice[8];
    float h2own[8];
    float oplog[16];
    unsigned keys2[NSTEP * 2];
    int nodeIdx, opIdx, sel;
    float nodeLp, nodeEnt, opLp, opEnt, lpSum, entSum;
    unsigned base;
};

// --------------------------- tagged publish/poll ---------------------------
__device__ __forceinline__ void pub64(u64t* p, float v, unsigned tag) {
    u64t w = ((u64t)tag << 32) | (u64t)__float_as_uint(v);
    asm volatile("st.relaxed.gpu.global.u64 [%0], %1;" :: "l"(p), "l"(w) : "memory");
}
__device__ __forceinline__ u64t ldrx(const u64t* p) {
    u64t w;
    asm volatile("ld.relaxed.gpu.global.u64 %0, [%1];" : "=l"(w) : "l"(p) : "memory");
    return w;
}
__device__ __forceinline__ float lo32(u64t w) { return __uint_as_float((unsigned)w); }

// ------------------------------ threefry2x32 -------------------------------
__device__ __forceinline__ void tf2x32(unsigned k0, unsigned k1,
                                       unsigned x0, unsigned x1,
                                       unsigned& o0, unsigned& o1) {
    unsigned ks2 = k0 ^ k1 ^ 0x1BD11BDAu;
    x0 += k0; x1 += k1;
#define TFR(r) { x0 += x1; x1 = (x1 << (r)) | (x1 >> (32 - (r))); x1 ^= x0; }
    TFR(13) TFR(15) TFR(26) TFR(6)   x0 += k1;  x1 += ks2 + 1u;
    TFR(17) TFR(29) TFR(16) TFR(24)  x0 += ks2; x1 += k0 + 2u;
    TFR(13) TFR(15) TFR(26) TFR(6)   x0 += k0;  x1 += k1 + 3u;
    TFR(17) TFR(29) TFR(16) TFR(24)  x0 += k1;  x1 += ks2 + 4u;
    TFR(13) TFR(15) TFR(26) TFR(6)   x0 += ks2; x1 += k0 + 5u;
#undef TFR
    o0 = x0; o1 = x1;
}

__device__ __forceinline__ float gumbelf(unsigned bits) {
    float f = __uint_as_float((bits >> 9) | 0x3f800000u) - 1.0f;
    const float tiny = 1.17549435e-38f;
    float u = fmaxf(tiny, f * (1.0f - tiny) + tiny);
    return -logf(-logf(u));
}

// fast transcendentals (~1e-6 rel err, far inside 1e-3 tolerance)
__device__ __forceinline__ float sigf(float x) {
    return __fdividef(1.0f, 1.0f + __expf(-x));
}
__device__ __forceinline__ float tanhfast(float x) {
    return 1.0f - __fdividef(2.0f, __expf(2.0f * x) + 1.0f);
}

// ----------------- LSTM cell: gates = Whh*hin + xc; update c,h -------------
__device__ __forceinline__ void cell_hh(SM* s, const float* hin, const float* xc,
                                        int tid, float* houtOwn) {
    int row = tid >> 4, lane = tid & 15;
    const float4* wp = (const float4*)&s->Whh[row * 512];
    const float4* vp = (const float4*)hin;
    float acc = 0.f;
#pragma unroll
    for (int i = 0; i < 8; i++) {
        float4 w = wp[i * 16 + lane], v = vp[i * 16 + lane];
        acc += w.x * v.x + w.y * v.y + w.z * v.z + w.w * v.w;
    }
#pragma unroll
    for (int o = 8; o; o >>= 1) acc += __shfl_down_sync(0xffffffffu, acc, o, 16);
    if (lane == 0) s->gbuf[row] = acc + xc[row];
    __syncthreads();
    if (tid < 8) {
        float gi = s->gbuf[tid],      gf = s->gbuf[8 + tid];
        float gg = s->gbuf[16 + tid], go = s->gbuf[24 + tid];
        float c2 = sigf(gf) * s->cslice[tid] + sigf(gi) * tanhfast(gg);
        float h2 = sigf(go) * tanhfast(c2);
        s->cslice[tid] = c2;
        houtOwn[tid] = h2;
    }
    __syncthreads();
}

// 8 dots of an 8x512 smem matrix with v (threads 0..127), conflict-free.
__device__ __forceinline__ void attn_dot(const float* M, const float* v,
                                         float* dst, int tid) {
    if (tid < 128) {
        int r = tid >> 4, lane = tid & 15;
        const float4* mp = (const float4*)&M[r * 512];
        const float4* vp = (const float4*)v;
        float acc = 0.f;
#pragma unroll
        for (int i = 0; i < 8; i++) {
            float4 w = mp[i * 16 + lane], x = vp[i * 16 + lane];
            acc += w.x * x.x + w.y * x.y + w.z * x.z + w.w * x.w;
        }
#pragma unroll
        for (int o = 8; o; o >>= 1) acc += __shfl_down_sync(0xffffffffu, acc, o, 16);
        if (lane == 0) dst[r] = acc;
    }
}

// ----- warp-parallel categorical sample + lp + entropy (tid<32 only) -------
__device__ __forceinline__ void warp_sample(const float* vals, const float* g, int n,
                                            int* oIdx, float* oLp, float* oEnt, int lane) {
    const float NINF = __int_as_float(0xff800000);
    float v1 = (lane < n) ? vals[lane] : NINF;
    float d1 = (lane < n) ? v1 + g[lane] : NINF;
    int   i1 = lane;
    float v2 = NINF;
    if (lane == 0 && n > 32) {
        v2 = vals[32];
        float d2 = v2 + g[32];
        if (d2 > d1) { d1 = d2; i1 = 32; }
    }
#pragma unroll
    for (int off = 16; off; off >>= 1) {
        float dv = __shfl_down_sync(0xffffffffu, d1, off);
        int   di = __shfl_down_sync(0xffffffffu, i1, off);
        if (dv > d1 || (dv == d1 && di < i1)) { d1 = dv; i1 = di; }
    }
    int best = __shfl_sync(0xffffffffu, i1, 0);
    float m1 = (lane < n) ? v1 : NINF;
    if (lane == 0 && n > 32) m1 = fmaxf(m1, v2);
#pragma unroll
    for (int off = 16; off; off >>= 1) m1 = fmaxf(m1, __shfl_xor_sync(0xffffffffu, m1, off));
    float se = (lane < n) ? __expf(v1 - m1) : 0.f;
    if (lane == 0 && n > 32) se += __expf(v2 - m1);
#pragma unroll
    for (int off = 16; off; off >>= 1) se += __shfl_xor_sync(0xffffffffu, se, off);
    float lse = __logf(se);
    float ent = 0.f;
    if (lane < n)            { float l = v1 - m1 - lse; ent -= l * __expf(l); }
    if (lane == 0 && n > 32) { float l = v2 - m1 - lse; ent -= l * __expf(l); }
#pragma unroll
    for (int off = 16; off; off >>= 1) ent += __shfl_xor_sync(0xffffffffu, ent, off);
    if (lane == 0) {
        *oIdx = best;
        *oLp  = -(vals[best] - m1 - lse);
        *oEnt = ent;
    }
}

__global__ void __launch_bounds__(NT, 1)
controller_kernel(const float* __restrict__ emb,   const float* __restrict__ w_ih,
                  const float* __restrict__ w_hh,  const float* __restrict__ b_ih,
                  const float* __restrict__ b_hh,  const float* __restrict__ w1,
                  const float* __restrict__ w2,    const float* __restrict__ idxfc,
                  const float* __restrict__ opfc,  float* __restrict__ out) {
    if (blockIdx.x >= GRID) return;   // throttle-avoidance dummies
    extern __shared__ __align__(16) float smraw[];
    SM* s = (SM*)smraw;
    const int tid = threadIdx.x;
    const int b   = blockIdx.x;

    // ---------------- setup ----------------
    if (tid == 0) {
        s->base = *(volatile unsigned*)&gEpochBase;
        s->sel = OPSN;
        s->lpSum = 0.f; s->entSum = 0.f;
    }
    for (int i = tid; i < 32 * 512; i += NT) {
        int row = i >> 9, k = i & 511;
        int gate = row >> 3, jj = row & 7;
        int grow = gate * 512 + b * 8 + jj;
        s->Whh[i] = w_hh[grow * 512 + k];
        s->Wih[i] = w_ih[grow * 512 + k];
    }
    for (int i = tid; i < 8 * 512; i += NT) {
        int a = i >> 9, k = i & 511;
        s->A1[i]  = w1[(b * 8 + a) * 512 + k];
        s->A2T[i] = w2[k * 512 + b * 8 + a];
    }
    if (tid < OPSN * 8) {
        int o = tid >> 3, j = tid & 7;
        s->OPFT[tid] = opfc[o * 512 + b * 8 + j];
    }
    if (tid < 32) {
        int gate = tid >> 3, jj = tid & 7;
        int grow = gate * 512 + b * 8 + jj;
        float bb = b_ih[grow] + b_hh[grow];
        s->bias[tid]  = bb;
        s->anchG[tid] = bb;      // anchor 0 = zeros -> x-gates = bias
    }
    if (tid < 8) { s->idxfc8[tid] = idxfc[b * 8 + tid]; s->cslice[tid] = 0.f; }
    if (tid < LP1 * 8) s->anchW1[tid] = 0.f;
    __syncthreads();

    // embGates for all 17 embeddings
    {
        int row = tid >> 4, lane = tid & 15;
        const float4* wr = (const float4*)&s->Wih[row * 512];
        for (int e = 0; e < 17; e++) {
            const float4* er = (const float4*)&emb[e * 512];
            float acc = 0.f;
#pragma unroll
            for (int i = 0; i < 8; i++) {
                float4 w = wr[i * 16 + lane];
                float4 v = __ldg(&er[i * 16 + lane]);
                acc += w.x * v.x + w.y * v.y + w.z * v.z + w.w * v.w;
            }
#pragma unroll
            for (int o = 8; o; o >>= 1) acc += __shfl_down_sync(0xffffffffu, acc, o, 16);
            if (lane == 0) s->embG[e * 32 + row] = acc + s->bias[row];
        }
    }
    // key chain (data-independent)
    if (tid == 0) {
        unsigned k0 = 0u, k1 = 42u;
        for (int t = 0; t < NSTEP; t++) {
            s->keys2[2 * t] = k0; s->keys2[2 * t + 1] = k1;
            unsigned o0, o1; tf2x32(k0, k1, 0u, 2u, o0, o1);
            k0 = o0; k1 = o1;
        }
    }
    __syncthreads();
    for (int p = tid; p < NSTEP * (LP1 + OPSN); p += NT) {
        int t = p / (LP1 + OPSN), r = p % (LP1 + OPSN);
        unsigned K0 = s->keys2[2 * t], K1 = s->keys2[2 * t + 1];
        unsigned c0, c1, o0, o1;
        if (r < LP1) {
            tf2x32(K0, K1, 0u, 0u, c0, c1);
            tf2x32(c0, c1, 0u, (unsigned)r, o0, o1);
            s->gnode[t * LP1 + r] = gumbelf(o0 ^ o1);
        } else {
            int o = r - LP1;
            tf2x32(K0, K1, 0u, 1u, c0, c1);
            tf2x32(c0, c1, 0u, (unsigned)o, o0, o1);
            s->gop[t * OPSN + o] = gumbelf(o0 ^ o1);
        }
    }
    __syncthreads();
    const unsigned base = s->base;

    // ---------------- initial cell: h0 = cell(emb[16], 0, 0) ----------------
    if (tid < 8) {
        float gi = s->embG[16 * 32 + tid];
        float gg = s->embG[16 * 32 + 16 + tid], go = s->embG[16 * 32 + 24 + tid];
        float c2 = sigf(gi) * tanhfast(gg);
        float h2 = sigf(go) * tanhfast(c2);
        s->cslice[tid] = c2;
        pub64(&gPubI[b * 8 + tid], h2, base + 1);
    }
    {   // all threads gather full h0
        int c = tid >> 3, p = tid & 7;
        u64t w;
        do { w = ldrx(&gPubI[c * 8 + p]); } while ((unsigned)(w >> 32) != base + 1);
        s->hprev[c * 8 + p] = lo32(w);
    }
    __syncthreads();
    if (b == 0 && tid == 0) *(volatile unsigned*)&gEpochBase = base + 128;

    // ---------------- main loop ----------------
    for (int t = 0; t < NSTEP; t++) {
        const unsigned tag1 = base + 2 + 3 * t;
        const unsigned tag2 = tag1 + 1;
        const unsigned tag3 = tag1 + 2;

        // cell1: h1 = cell(emb[sel], hprev, c)
        cell_hh(s, s->hprev, &s->embG[s->sel * 32], tid, &s->h1full[b * 8]);

        // publish round1: attn partial for global dim `tid`, + own h1 slice
        {
            float pa = 0.f;
#pragma unroll
            for (int j = 0; j < 8; j++)
                pa += s->A2T[j * 512 + tid] * s->h1full[b * 8 + j];
            pub64(&gPubA[b * 512 + tid], pa, tag1);
            if (tid < 8) pub64(&gPubH1[b * 8 + tid], s->h1full[b * 8 + tid], tag1);
        }

        // overlap comm latency: anchor-t x-gates + anchW1[t] from hprev
        if (t > 0) {
            int row = tid >> 4, lane = tid & 15;
            const float4* wp = (const float4*)&s->Wih[row * 512];
            const float4* vp = (const float4*)s->hprev;
            float acc = 0.f;
#pragma unroll
            for (int i = 0; i < 8; i++) {
                float4 w = wp[i * 16 + lane], v = vp[i * 16 + lane];
                acc += w.x * v.x + w.y * v.y + w.z * v.z + w.w * v.w;
            }
#pragma unroll
            for (int o = 8; o; o >>= 1) acc += __shfl_down_sync(0xffffffffu, acc, o, 16);
            if (lane == 0) s->anchG[t * 32 + row] = acc + s->bias[row];
        }
        attn_dot(s->A1, s->hprev, &s->anchW1[t * 8], tid);
        __syncthreads();   // (A) anchW1/anchG ready; all published

        // consume round1: batched 2-poll per thread
        {
            int c = tid >> 3, p = tid & 7;
            const u64t* q0 = &gPubA[c * 512 + b * 8 + p];
            const u64t* q1 = &gPubH1[c * 8 + p];
            float v0 = 0.f, v1 = 0.f;
            unsigned got = 0;
            while (got != 3u) {
                u64t w;
                if (!(got & 1u)) { w = ldrx(q0); if ((unsigned)(w >> 32) == tag1) { v0 = lo32(w); got |= 1u; } }
                if (!(got & 2u)) { w = ldrx(q1); if ((unsigned)(w >> 32) == tag1) { v1 = lo32(w); got |= 2u; } }
            }
            s->attnP[p * 64 + c]  = v0;
            s->h1full[c * 8 + p]  = v1;
        }
        __syncthreads();   // (B)
        if (tid < 8) {
            const float4* ap = (const float4*)&s->attnP[tid * 64];
            float sacc = 0.f;
#pragma unroll
            for (int i = 0; i < 16; i++) { float4 v = ap[i]; sacc += v.x + v.y + v.z + v.w; }
            s->hw2s[tid] = sacc;
        }
        __syncthreads();   // (C)

        // node-logit partial for own 8 dims, anchors 0..t; publish
        if (tid < 288) {
            int a = tid >> 3; if (a > 32) a = 32;
            int rl = tid & 7;
            float q = tanhfast(s->anchW1[a * 8 + rl] + s->hw2s[rl]) * s->idxfc8[rl];
#pragma unroll
            for (int o = 4; o; o >>= 1) q += __shfl_down_sync(0xffffffffu, q, o, 8);
            if (rl == 0 && tid < 264 && a <= t) pub64(&gPubL[a * 64 + b], q, tag2);
        }

        // consume round2: (t+1)*64 words, batched <=4 polls per thread
        {
            int cnt = (t + 1) * 64;
            int k0 = tid, k1 = tid + 512, k2 = tid + 1024, k3 = tid + 1536;
            unsigned need = (k0 < cnt ? 1u : 0u) | (k1 < cnt ? 2u : 0u) |
                            (k2 < cnt ? 4u : 0u) | (k3 < cnt ? 8u : 0u);
            unsigned got = 0;
            float v0 = 0.f, v1 = 0.f, v2 = 0.f, v3 = 0.f;
            while (got != need) {
                u64t w;
                if ((need & 1u) && !(got & 1u)) { w = ldrx(&gPubL[k0]); if ((unsigned)(w >> 32) == tag2) { v0 = lo32(w); got |= 1u; } }
                if ((need & 2u) && !(got & 2u)) { w = ldrx(&gPubL[k1]); if ((unsigned)(w >> 32) == tag2) { v1 = lo32(w); got |= 2u; } }
                if ((need & 4u) && !(got & 4u)) { w = ldrx(&gPubL[k2]); if ((unsigned)(w >> 32) == tag2) { v2 = lo32(w); got |= 4u; } }
                if ((need & 8u) && !(got & 8u)) { w = ldrx(&gPubL[k3]); if ((unsigned)(w >> 32) == tag2) { v3 = lo32(w); got |= 8u; } }
            }
            if (need & 1u) s->lsum[k0] = v0;
            if (need & 2u) s->lsum[k1] = v1;
            if (need & 4u) s->lsum[k2] = v2;
            if (need & 8u) s->lsum[k3] = v3;
        }
        __syncthreads();   // (D)
        if (tid < LP1) {
            float v;
            if (tid <= t) {
                const float4* lp = (const float4*)&s->lsum[tid * 64];
                v = 0.f;
#pragma unroll
                for (int i = 0; i < 16; i++) { float4 x = lp[i]; v += x.x + x.y + x.z + x.w; }
                v = 2.5f * tanhfast(v * 0.2f);
            } else v = -1e9f;
            s->vals[tid] = v;
        }
        __syncthreads();   // (E)
        if (tid < 32)
            warp_sample(s->vals, &s->gnode[t * LP1], LP1,
                        &s->nodeIdx, &s->nodeLp, &s->nodeEnt, tid);
        __syncthreads();   // (F)

        // cell2: h2 = cell(anchor[nodeIdx], h1, c)
        cell_hh(s, s->h1full, &s->anchG[s->nodeIdx * 32], tid, s->h2own);

        // publish round3: h2 slice + op partials (24 words)
        if (tid < 8) {
            pub64(&gPubO[b * 24 + tid], s->h2own[tid], tag3);
        } else if (tid < 24) {
            int o = tid - 8;
            float oa = 0.f;
#pragma unroll
            for (int j = 0; j < 8; j++) oa += s->OPFT[o * 8 + j] * s->h2own[j];
            pub64(&gPubO[b * 24 + 8 + o], oa, tag3);
        }

        // consume round3: 1536 words, batched 3 polls per thread
        {
            int k0 = tid, k1 = tid + 512, k2 = tid + 1024;
            unsigned got = 0;
            float v0 = 0.f, v1 = 0.f, v2 = 0.f;
            while (got != 7u) {
                u64t w;
                if (!(got & 1u)) { w = ldrx(&gPubO[k0]); if ((unsigned)(w >> 32) == tag3) { v0 = lo32(w); got |= 1u; } }
                if (!(got & 2u)) { w = ldrx(&gPubO[k1]); if ((unsigned)(w >> 32) == tag3) { v1 = lo32(w); got |= 2u; } }
                if (!(got & 4u)) { w = ldrx(&gPubO[k2]); if ((unsigned)(w >> 32) == tag3) { v2 = lo32(w); got |= 4u; } }
            }
            int c0 = k0 / 24, i0 = k0 - c0 * 24;
            int c1 = k1 / 24, i1 = k1 - c1 * 24;
            int c2 = k2 / 24, i2 = k2 - c2 * 24;
            if (i0 < 8) s->hprev[c0 * 8 + i0] = v0; else s->opP[(i0 - 8) * 64 + c0] = v0;
            if (i1 < 8) s->hprev[c1 * 8 + i1] = v1; else s->opP[(i1 - 8) * 64 + c1] = v1;
            if (i2 < 8) s->hprev[c2 * 8 + i2] = v2; else s->opP[(i2 - 8) * 64 + c2] = v2;
        }
        __syncthreads();   // (G)

        // warp0: op logits + sample + bookkeeping
        if (tid < 32) {
            if (tid < 16) {
                const float4* op = (const float4*)&s->opP[tid * 64];
                float osum = 0.f;
#pragma unroll
                for (int i = 0; i < 16; i++) { float4 v = op[i]; osum += v.x + v.y + v.z + v.w; }
                s->oplog[tid] = tanhfast(osum * 0.2f);
            }
            __syncwarp();
            warp_sample(s->oplog, &s->gop[t * OPSN], OPSN,
                        &s->opIdx, &s->opLp, &s->opEnt, tid);
            if (tid == 0) {
                s->lpSum  += s->nodeLp + s->opLp;
                s->entSum += s->nodeEnt + s->opEnt;
                s->sel = s->opIdx;
                if (b == 0) {
                    out[2 * t]     = (float)s->nodeIdx;
                    out[2 * t + 1] = (float)s->opIdx;
                }
            }
        }
        __syncthreads();   // (H)
    }

    if (b == 0 && tid == 0) { out[64] = s->entSum; out[65] = s->lpSum; }
}

extern "C" void kernel_launch(void* const* d_in, const int* in_sizes, int n_in,
                              void* d_out, int out_size) {
    (void)in_sizes; (void)n_in; (void)out_size;
    cudaFuncSetAttribute(controller_kernel,
                         cudaFuncAttributeMaxDynamicSharedMemorySize,
                         (int)sizeof(SM));
    controller_kernel<<<GRIDL, NT, sizeof(SM)>>>(
        (const float*)d_in[0],  // embedding
        (const float*)d_in[1],  // w_ih
        (const float*)d_in[2],  // w_hh
        (const float*)d_in[3],  // b_ih
        (const float*)d_in[4],  // b_hh
        (const float*)d_in[5],  // w_attn_1
        (const float*)d_in[6],  // w_attn_2
        (const float*)d_in[7],  // index_fc
        (const float*)d_in[8],  // op_fc
        (float*)d_out);
}